// round 13
// baseline (speedup 1.0000x reference)
#include <cuda_runtime.h>
#include <cuda_fp16.h>
#include <cstdint>
#include <math.h>

#define BATCH 8
#define CIN   512
#define COUT  512
#define WDIM  512
#define INS   64
#define Y1S   66
#define PLANE 4356
#define UPS   138
#define OUTS  64
#define KTOT  4608
#define XPH   68
#define XPW   72
#define XPL   (XPH*XPW)   // 4896
#define XSP   5376        // copy size: 4896 plane + 3*160 special region
#define SPEC  4896

__device__ float    g_styles[BATCH*CIN];
__device__ float    g_filter[12];
__device__ __half   g_wh[COUT*KTOT];
__device__ float    g_d[BATCH*COUT];
__device__ float    g_y1[BATCH*COUT*PLANE];
// 3 column-shifted (dc=0,1,2) copies of the padded plane + per-dr gathered
// rows for the 5 non-contiguous atoms. Layout: [(b*CIN+c)*3 + dc][XSP].
__device__ __align__(16) __half g_xs[(size_t)BATCH*CIN*3*XSP];

// ---------------- PTX helpers (sm_80-baseline only) ----------------
__device__ __forceinline__ uint32_t smem_u32(const void* p) {
    uint32_t a;
    asm("{ .reg .u64 t; cvta.to.shared.u64 t, %1; cvt.u32.u64 %0, t; }" : "=r"(a) : "l"(p));
    return a;
}
#define CP16(dst, src) \
    asm volatile("cp.async.cg.shared.global [%0], [%1], 16;" :: "r"(dst), "l"(src))
#define CP16Z(dst, src, sz) \
    asm volatile("cp.async.cg.shared.global [%0], [%1], 16, %2;" :: "r"(dst), "l"(src), "r"(sz))
#define CPC() asm volatile("cp.async.commit_group;")
#define LDSM4(R, ad) \
    asm volatile("ldmatrix.sync.aligned.m8n8.x4.shared.b16 {%0,%1,%2,%3}, [%4];" \
        : "=r"((R)[0]), "=r"((R)[1]), "=r"((R)[2]), "=r"((R)[3]) : "r"(ad))
#define LDSM4T(R, ad) \
    asm volatile("ldmatrix.sync.aligned.m8n8.x4.trans.shared.b16 {%0,%1,%2,%3}, [%4];" \
        : "=r"((R)[0]), "=r"((R)[1]), "=r"((R)[2]), "=r"((R)[3]) : "r"(ad))
#define MMA(d, a, b0, b1) \
    asm volatile("mma.sync.aligned.m16n8k16.row.col.f32.f16.f16.f32 " \
        "{%0,%1,%2,%3}, {%4,%5,%6,%7}, {%8,%9}, {%0,%1,%2,%3};" \
        : "+f"((d)[0]), "+f"((d)[1]), "+f"((d)[2]), "+f"((d)[3]) \
        : "r"((a)[0]), "r"((a)[1]), "r"((a)[2]), "r"((a)[3]), "r"(b0), "r"(b1))

// atom(32px) -> plane pixel map; atoms 0..136 real.
__device__ __forceinline__ bool atom_pix(int a, int j, int& P, int& Q) {
    if (a >= 137) return false;
    if (a < 132) {
        int blk = a / 33, ww = a - blk * 33;
        if (ww < 32) { P = blk*16 + (ww>>1); Q = ((ww&1)<<5) + j; return true; }
        P = blk*16 + (j>>1); Q = 64 + (j&1); return true;
    }
    if (a < 136) { int ww = a - 132; P = 64 + (ww>>1); Q = ((ww&1)<<5) + j; return true; }
    P = 64 + (j>>1); Q = 64 + (j&1); return (j < 4);
}
__device__ double bessel_i0(double x) {
    double t = x*x*0.25, term = 1.0, s = 1.0;
    for (int k = 1; k < 64; k++) { term *= t/((double)k*(double)k); s += term; if (term < 1e-18*s) break; }
    return s;
}

// ============ K0: filter + styles + global style norm ============
__global__ void k0_styles(const float* __restrict__ w, const float* __restrict__ A,
                          const float* __restrict__ bias) {
    int i = threadIdx.x;
    if (i == 0) {
        const double PI = 3.14159265358979323846;
        double a = 2.285*11.0*PI*0.5 + 7.95;
        double beta = (a > 50.0) ? 0.1102*(a-8.7)
                     : (a > 21.0) ? 0.5842*pow(a-21.0,0.4)+0.07886*(a-21.0) : 0.0;
        double i0b = bessel_i0(beta), h[12], sum = 0.0;
        for (int n = 0; n < 12; n++) {
            double m = n - 5.5, sx = 0.5*m;
            double sinc = (sx==0.0) ? 1.0 : sin(PI*sx)/(PI*sx);
            double rt = m/5.5;
            h[n] = 0.5*sinc*bessel_i0(beta*sqrt(fmax(0.0,1.0-rt*rt)))/i0b;
            sum += h[n];
        }
        for (int n = 0; n < 12; n++) g_filter[n] = (float)(h[n]/sum);
    }
    float acc[BATCH];
#pragma unroll
    for (int b = 0; b < BATCH; b++) acc[b] = 0.f;
    const float* Ai = A + (size_t)i*WDIM;
    for (int k = 0; k < WDIM; k++) {
        float av = Ai[k];
#pragma unroll
        for (int b = 0; b < BATCH; b++) acc[b] += w[b*WDIM+k]*av;
    }
    float bi = bias[i], p = 0.f;
#pragma unroll
    for (int b = 0; b < BATCH; b++) { acc[b] = acc[b]*0.04419417382415922f + bi; p += acc[b]*acc[b]; }
    __shared__ float red[512];
    red[i] = p; __syncthreads();
    for (int s = 256; s > 0; s >>= 1) { if (i < s) red[i] += red[i+s]; __syncthreads(); }
    float sc = rsqrtf(red[0]*(1.0f/(BATCH*CIN)));
#pragma unroll
    for (int b = 0; b < BATCH; b++) g_styles[b*CIN+i] = acc[b]*sc;
}

// ============ K1: weight norm + fp16 + demod ============
__global__ void k1_wnorm(const float* __restrict__ cw) {
    int o = blockIdx.x, tid = threadIdx.x;
    const float* wo = cw + (size_t)o*(CIN*9);
    __shared__ float red[256];
    float ss = 0.f;
    for (int t = tid; t < CIN*9; t += 256) { float v = wo[t]; ss += v*v; }
    red[tid] = ss; __syncthreads();
    for (int s = 128; s > 0; s >>= 1) { if (tid < s) red[tid] += red[tid+s]; __syncthreads(); }
    float r = rsqrtf(red[0]*(1.0f/(CIN*9)));
    __syncthreads();
    for (int t = tid; t < CIN*9; t += 256) {
        int i = t/9, kk = t - i*9;
        g_wh[(size_t)o*KTOT + kk*512 + i] = __float2half_rn(wo[t]*r);
    }
    float r2 = r*r;
    float part[BATCH];
#pragma unroll
    for (int b = 0; b < BATCH; b++) part[b] = 0.f;
    for (int i = tid; i < CIN; i += 256) {
        float s9 = 0.f;
#pragma unroll
        for (int k = 0; k < 9; k++) { float v = wo[i*9+k]; s9 += v*v; }
        float w2 = s9*r2;
#pragma unroll
        for (int b = 0; b < BATCH; b++) {
            float sv = g_styles[b*CIN+i];
            part[b] += sv*sv*w2;
        }
    }
#pragma unroll
    for (int b = 0; b < BATCH; b++) {
        red[tid] = part[b]; __syncthreads();
        for (int s = 128; s > 0; s >>= 1) { if (tid < s) red[tid] += red[tid+s]; __syncthreads(); }
        if (tid == 0) g_d[b*COUT+o] = rsqrtf(red[0] + 1e-8f);
        __syncthreads();
    }
}

// ============ K_pad: 3 shifted fp16 copies + gathered special atoms ==========
__global__ void k_pad(const float* __restrict__ x) {
    size_t idx = (size_t)blockIdx.x*256 + threadIdx.x;
    if (idx >= (size_t)BATCH*CIN*3*XSP) return;
    int e  = (int)(idx % XSP);
    int dc = (int)((idx / XSP) % 3);
    int bc = (int)(idx / ((size_t)XSP*3));
    int P, Q;
    bool val = true;
    if (e < SPEC) {
        P = e / XPW; Q = e - P*XPW + dc;
    } else {
        int e2 = e - SPEC;
        int dr = e2 / 160, rem = e2 - dr*160;
        int s = rem >> 5, j = rem & 31;
        const int SA[5] = {32, 65, 98, 131, 136};
        int PP, QQ;
        if (atom_pix(SA[s], j, PP, QQ)) { P = PP + dr; Q = QQ + dc; }
        else val = false;
    }
    float v = 0.f;
    if (val) {
        int ri = P - 2, ci = Q - 2;
        if (ri >= 0 && ri < INS && ci >= 0 && ci < INS)
            v = x[((size_t)bc*INS + ri)*INS + ci] * g_styles[bc];
    }
    g_xs[idx] = __float2half_rn(v);
}

// ============ K_gemm: HMMA fp16, all-cp.async, 3-stage ============
// stage bytes: A[128][40] = 10240 | B[32 rows][272B] = 8704  => 18944
#define STG_BYTES 18944
#define GEMM_SMEM (3*STG_BYTES)        // 56832
#define NCH 144

__global__ __launch_bounds__(256, 2)
void k_gemm(const float* __restrict__ cbias) {
    extern __shared__ __align__(16) char smraw[];
    uint32_t sb = smem_u32(smraw);
    int tid = threadIdx.x, w = tid >> 5, lane = tid & 31;
    int nt = blockIdx.x, oc0 = blockIdx.y * 128, bz = blockIdx.z;
    int wm = w & 1, wn = w >> 1;
    int m0 = wm * 64, n0 = wn * 32;

    // ---- B cp.async geometry: thread -> (k_local, atom, 32B half-row) ----
    int k_local = tid >> 3;            // 0..31
    int a_local = (tid >> 1) & 3;      // 0..3
    int hq = tid & 1;                  // which 32B half of the 64B atom row
    int aG = nt*4 + a_local;
    int baseoff, drs; uint32_t csz;
    if (aG >= 137)                       { baseoff = 0; drs = 0; csz = 0; }
    else if (aG == 136)                  { baseoff = SPEC + 4*32; drs = 160; csz = 16; }
    else if (aG < 132 && (aG % 33) == 32){ baseoff = SPEC + (aG/33)*32; drs = 160; csz = 16; }
    else { int P, Q; atom_pix(aG, 0, P, Q); baseoff = P*XPW + Q; drs = XPW; csz = 16; }
    uint32_t bdst0 = (uint32_t)(10240 + k_local*272 + a_local*64 + hq*32);

    // ---- A geometry: thread t loads row t>>1, half t&1 (2x CP16) ----
    int arow = tid >> 1, ahalf = tid & 1;
    uint32_t adst0 = (uint32_t)((arow*40 + ahalf*16) * 2);

    // ---- ldmatrix base offsets (bytes from stage base) ----
    uint32_t a_base = (uint32_t)(((m0 + (lane & 15))*40 + ((lane >> 4)*8)) * 2);
    uint32_t b_base = (uint32_t)((5120 + ((lane & 7) + ((lane >> 3) & 1)*8)*136
                                  + n0 + ((lane >> 4)*8)) * 2);

    float acc[64];
#pragma unroll
    for (int t = 0; t < 64; t++) acc[t] = 0.f;

    auto issue = [&](int ch, int st) {
        // A
        const __half* asrc = g_wh + (size_t)(oc0 + arow)*KTOT + ch*32 + ahalf*16;
        uint32_t ad = sb + (uint32_t)(st*STG_BYTES) + adst0;
        CP16(ad,      asrc);
        CP16(ad + 16, asrc + 8);
        // B
        int tap = ch >> 4, dr = tap/3, dc = tap - dr*3;
        int icb = (ch & 15) << 5;
        const __half* bsrc = g_xs
            + ((size_t)(bz*CIN + icb + k_local)*3 + dc)*XSP
            + baseoff + dr*drs + hq*16;
        uint32_t bd = sb + (uint32_t)(st*STG_BYTES) + bdst0;
        CP16Z(bd,      bsrc,     csz);
        CP16Z(bd + 16, bsrc + 8, csz);
        CPC();
    };

    issue(0, 0);
    issue(1, 1);

    for (int ch = 0; ch < NCH; ch++) {
        int st = ch % 3;
        asm volatile("cp.async.wait_group 1;");
        __syncthreads();
        if (ch + 2 < NCH) issue(ch + 2, (ch + 2) % 3);

        uint32_t sbase = sb + (uint32_t)(st * STG_BYTES);
#pragma unroll
        for (int k16 = 0; k16 < 2; k16++) {
            uint32_t sA = sbase + a_base + k16*32;
            uint32_t sB = sbase + b_base + k16*(16*136*2);
            uint32_t ah[16], bh[8];
#pragma unroll
            for (int mt = 0; mt < 4; mt++) LDSM4(&ah[mt*4], sA + mt*1280);
#pragma unroll
            for (int n2 = 0; n2 < 2; n2++) LDSM4T(&bh[n2*4], sB + n2*32);
#pragma unroll
            for (int mt = 0; mt < 4; mt++)
#pragma unroll
                for (int n = 0; n < 4; n++)
                    MMA(&acc[(mt*4+n)*4], &ah[mt*4],
                        bh[(n>>1)*4 + (n&1)*2], bh[(n>>1)*4 + (n&1)*2 + 1]);
        }
    }

    // ---- epilogue: demod + bias, float2 stores ----
#pragma unroll
    for (int mt = 0; mt < 4; mt++) {
        int ocA = oc0 + m0 + mt*16 + (lane >> 2);
        float dmA = g_d[bz*COUT + ocA],     biA = cbias[ocA];
        float dmB = g_d[bz*COUT + ocA + 8], biB = cbias[ocA + 8];
        size_t rowA = ((size_t)(bz*COUT + ocA)) * PLANE;
        size_t rowB = rowA + (size_t)8 * PLANE;
#pragma unroll
        for (int n = 0; n < 4; n++) {
            int nl = n0 + n*8 + (lane & 3)*2;
            int P, Q;
            if (!atom_pix(nt*4 + (nl >> 5), nl & 31, P, Q)) continue;
            int po = P*Y1S + Q;
            float* c = &acc[(mt*4+n)*4];
            *(float2*)(g_y1 + rowA + po) = make_float2(c[0]*dmA + biA, c[1]*dmA + biA);
            *(float2*)(g_y1 + rowB + po) = make_float2(c[2]*dmB + biB, c[3]*dmB + biB);
        }
    }
}

// ============ K4: paired-polyphase fused FIR (fp16 act, stride 140) ======
// smem: vt 9108 f32 (36432B) | act 138x140 f16 (38640B) => 75072B, 3 CTAs/SM
#define K4_VT_BYTES  (9108*4)
#define K4_SMEM      (K4_VT_BYTES + 138*140*2)

__global__ __launch_bounds__(512, 3)
void k4_fir(float* __restrict__ out) {
    int plane = blockIdx.x, tid = threadIdx.x;
    extern __shared__ char sm4[];
    float*  vt  = (float*)sm4;
    __half* act = (__half*)(sm4 + K4_VT_BYTES);
    const float* src = g_y1 + (size_t)plane*PLANE;
    float fl[12];
#pragma unroll
    for (int k = 0; k < 12; k++) fl[k] = g_filter[k];

    // phase 1: vertical up-FIR, paired rows (2m, 2m+1). 69 pairs x 66 cols.
    for (int e = tid; e < 69*Y1S; e += 512) {
        int m = e / Y1S, i = e - m*Y1S;
        float s[6];
#pragma unroll
        for (int j = 0; j < 6; j++) {
            int row = m - 4 + j;
            s[j] = ((unsigned)row < 66u) ? src[row*Y1S + i] : 0.f;
        }
        float ev = s[0]*fl[10] + s[1]*fl[8] + s[2]*fl[6] + s[3]*fl[4] + s[4]*fl[2] + s[5]*fl[0];
        float od = s[0]*fl[11] + s[1]*fl[9] + s[2]*fl[7] + s[3]*fl[5] + s[4]*fl[3] + s[5]*fl[1];
        vt[(2*m)*Y1S + i]   = 4.f*ev;
        vt[(2*m+1)*Y1S + i] = 4.f*od;
    }
    __syncthreads();

    // phase 2: horizontal up-FIR + lrelu + clamp, paired cols. 138 x 69.
    for (int e = tid; e < UPS*69; e += 512) {
        int r = e / 69, m = e - r*69;
        const float* vr = vt + r*Y1S;
        float s[6];
#pragma unroll
        for (int j = 0; j < 6; j++) {
            int c = m - 4 + j;
            s[j] = ((unsigned)c < 66u) ? vr[c] : 0.f;
        }
        float ev = s[0]*fl[10] + s[1]*fl[8] + s[2]*fl[6] + s[3]*fl[4] + s[4]*fl[2] + s[5]*fl[0];
        float od = s[0]*fl[11] + s[1]*fl[9] + s[2]*fl[7] + s[3]*fl[5] + s[4]*fl[3] + s[5]*fl[1];
        ev = (ev >= 0.f ? ev : 0.2f*ev)*1.4142135623730951f;
        od = (od >= 0.f ? od : 0.2f*od)*1.4142135623730951f;
        ev = fminf(fmaxf(ev, -256.f), 256.f);
        od = fminf(fmaxf(od, -256.f), 256.f);
        *(__half2*)(act + r*140 + 2*m) = __floats2half2_rn(ev, od);
    }
    __syncthreads();

    // phase 3: vertical down-FIR (stride-2 rows), half2 col pairs. 64 x 69.
    for (int e = tid; e < OUTS*69; e += 512) {
        int rr = e / 69, jj = e - rr*69;
        const __half2* ap = (const __half2*)(act + (2*rr)*140 + 2*jj);
        float ax = 0.f, ay = 0.f;
#pragma unroll
        for (int t = 0; t < 12; t++) {
            float2 v = __half22float2(ap[t*70]);
            ax += fl[11-t]*v.x;
            ay += fl[11-t]*v.y;
        }
        *(float2*)(vt + rr*UPS + 2*jj) = make_float2(ax, ay);
    }
    __syncthreads();

    // phase 4: horizontal down-FIR (stride 2), paired outputs. 64 x 32.
    float* dst = out + (size_t)plane*(OUTS*OUTS);
    for (int e = tid; e < OUTS*32; e += 512) {
        int rr = e >> 5, p = e & 31;
        const float* dp = vt + rr*UPS + 4*p;
        float d[14];
#pragma unroll
        for (int q = 0; q < 14; q++) d[q] = dp[q];
        float o0 = 0.f, o1 = 0.f;
#pragma unroll
        for (int t = 0; t < 12; t++) {
            o0 += fl[11-t]*d[t];
            o1 += fl[11-t]*d[t+2];
        }
        *(float2*)(dst + rr*OUTS + 2*p) = make_float2(o0, o1);
    }
}

// ============ launch ============
extern "C" void kernel_launch(void* const* d_in, const int* in_sizes, int n_in,
                              void* d_out, int out_size) {
    const float* x  = (const float*)d_in[0];
    const float* w  = (const float*)d_in[1];
    const float* A  = (const float*)d_in[2];
    const float* ab = (const float*)d_in[3];
    const float* cw = (const float*)d_in[4];
    const float* cb = (const float*)d_in[5];
    float* out = (float*)d_out;

    cudaFuncSetAttribute(k_gemm, cudaFuncAttributeMaxDynamicSharedMemorySize, GEMM_SMEM);
    cudaFuncSetAttribute(k4_fir, cudaFuncAttributeMaxDynamicSharedMemorySize, K4_SMEM);

    size_t npad = (size_t)BATCH*CIN*3*XSP;
    k0_styles<<<1, 512>>>(w, A, ab);
    k1_wnorm<<<COUT, 256>>>(cw);
    k_pad<<<(unsigned)((npad + 255)/256), 256>>>(x);
    k_gemm<<<dim3(35, 4, BATCH), 256, GEMM_SMEM>>>(cb);   // launch idx 3
    k4_fir<<<BATCH*COUT, 512, K4_SMEM>>>(out);
}

// round 14
// speedup vs baseline: 1.1077x; 1.1077x over previous
#include <cuda_runtime.h>
#include <cuda_fp16.h>
#include <cstdint>
#include <math.h>

#define BATCH 8
#define CIN   512
#define COUT  512
#define WDIM  512
#define INS   64
#define Y1S   66
#define PLANE 4356
#define UPS   138
#define OUTS  64
#define KTOT  4608
#define XPH   68
#define XPW   72
#define XPL   (XPH*XPW)   // 4896
#define XSP   5376        // copy size: 4896 plane + 3*160 special region
#define SPEC  4896

__device__ float    g_styles[BATCH*CIN];
__device__ float    g_filter[12];
__device__ __half   g_wh[COUT*KTOT];
__device__ float    g_d[BATCH*COUT];
__device__ float    g_y1[BATCH*COUT*PLANE];
// 3 column-shifted (dc=0,1,2) copies of the padded plane + per-dr gathered
// rows for the 5 non-contiguous atoms. Layout: [(b*CIN+c)*3 + dc][XSP].
__device__ __align__(16) __half g_xs[(size_t)BATCH*CIN*3*XSP];

// ---------------- PTX helpers (sm_80-baseline only) ----------------
__device__ __forceinline__ uint32_t smem_u32(const void* p) {
    uint32_t a;
    asm("{ .reg .u64 t; cvta.to.shared.u64 t, %1; cvt.u32.u64 %0, t; }" : "=r"(a) : "l"(p));
    return a;
}
#define CP16(dst, src) \
    asm volatile("cp.async.cg.shared.global [%0], [%1], 16;" :: "r"(dst), "l"(src))
#define CP16Z(dst, src, sz) \
    asm volatile("cp.async.cg.shared.global [%0], [%1], 16, %2;" :: "r"(dst), "l"(src), "r"(sz))
#define CPC() asm volatile("cp.async.commit_group;")
#define LDSM4(R, ad) \
    asm volatile("ldmatrix.sync.aligned.m8n8.x4.shared.b16 {%0,%1,%2,%3}, [%4];" \
        : "=r"((R)[0]), "=r"((R)[1]), "=r"((R)[2]), "=r"((R)[3]) : "r"(ad))
#define LDSM4T(R, ad) \
    asm volatile("ldmatrix.sync.aligned.m8n8.x4.trans.shared.b16 {%0,%1,%2,%3}, [%4];" \
        : "=r"((R)[0]), "=r"((R)[1]), "=r"((R)[2]), "=r"((R)[3]) : "r"(ad))
#define MMA(d, a, b0, b1) \
    asm volatile("mma.sync.aligned.m16n8k16.row.col.f32.f16.f16.f32 " \
        "{%0,%1,%2,%3}, {%4,%5,%6,%7}, {%8,%9}, {%0,%1,%2,%3};" \
        : "+f"((d)[0]), "+f"((d)[1]), "+f"((d)[2]), "+f"((d)[3]) \
        : "r"((a)[0]), "r"((a)[1]), "r"((a)[2]), "r"((a)[3]), "r"(b0), "r"(b1))

// atom(32px) -> plane pixel map; atoms 0..136 real.
__device__ __forceinline__ bool atom_pix(int a, int j, int& P, int& Q) {
    if (a >= 137) return false;
    if (a < 132) {
        int blk = a / 33, ww = a - blk * 33;
        if (ww < 32) { P = blk*16 + (ww>>1); Q = ((ww&1)<<5) + j; return true; }
        P = blk*16 + (j>>1); Q = 64 + (j&1); return true;
    }
    if (a < 136) { int ww = a - 132; P = 64 + (ww>>1); Q = ((ww&1)<<5) + j; return true; }
    P = 64 + (j>>1); Q = 64 + (j&1); return (j < 4);
}
__device__ double bessel_i0(double x) {
    double t = x*x*0.25, term = 1.0, s = 1.0;
    for (int k = 1; k < 64; k++) { term *= t/((double)k*(double)k); s += term; if (term < 1e-18*s) break; }
    return s;
}

// ============ K0: filter + styles + global style norm ============
__global__ void k0_styles(const float* __restrict__ w, const float* __restrict__ A,
                          const float* __restrict__ bias) {
    int i = threadIdx.x;
    if (i == 0) {
        const double PI = 3.14159265358979323846;
        double a = 2.285*11.0*PI*0.5 + 7.95;
        double beta = (a > 50.0) ? 0.1102*(a-8.7)
                     : (a > 21.0) ? 0.5842*pow(a-21.0,0.4)+0.07886*(a-21.0) : 0.0;
        double i0b = bessel_i0(beta), h[12], sum = 0.0;
        for (int n = 0; n < 12; n++) {
            double m = n - 5.5, sx = 0.5*m;
            double sinc = (sx==0.0) ? 1.0 : sin(PI*sx)/(PI*sx);
            double rt = m/5.5;
            h[n] = 0.5*sinc*bessel_i0(beta*sqrt(fmax(0.0,1.0-rt*rt)))/i0b;
            sum += h[n];
        }
        for (int n = 0; n < 12; n++) g_filter[n] = (float)(h[n]/sum);
    }
    float acc[BATCH];
#pragma unroll
    for (int b = 0; b < BATCH; b++) acc[b] = 0.f;
    const float* Ai = A + (size_t)i*WDIM;
    for (int k = 0; k < WDIM; k++) {
        float av = Ai[k];
#pragma unroll
        for (int b = 0; b < BATCH; b++) acc[b] += w[b*WDIM+k]*av;
    }
    float bi = bias[i], p = 0.f;
#pragma unroll
    for (int b = 0; b < BATCH; b++) { acc[b] = acc[b]*0.04419417382415922f + bi; p += acc[b]*acc[b]; }
    __shared__ float red[512];
    red[i] = p; __syncthreads();
    for (int s = 256; s > 0; s >>= 1) { if (i < s) red[i] += red[i+s]; __syncthreads(); }
    float sc = rsqrtf(red[0]*(1.0f/(BATCH*CIN)));
#pragma unroll
    for (int b = 0; b < BATCH; b++) g_styles[b*CIN+i] = acc[b]*sc;
}

// ============ K1: weight norm + fp16 + demod ============
__global__ void k1_wnorm(const float* __restrict__ cw) {
    int o = blockIdx.x, tid = threadIdx.x;
    const float* wo = cw + (size_t)o*(CIN*9);
    __shared__ float red[256];
    float ss = 0.f;
    for (int t = tid; t < CIN*9; t += 256) { float v = wo[t]; ss += v*v; }
    red[tid] = ss; __syncthreads();
    for (int s = 128; s > 0; s >>= 1) { if (tid < s) red[tid] += red[tid+s]; __syncthreads(); }
    float r = rsqrtf(red[0]*(1.0f/(CIN*9)));
    __syncthreads();
    for (int t = tid; t < CIN*9; t += 256) {
        int i = t/9, kk = t - i*9;
        g_wh[(size_t)o*KTOT + kk*512 + i] = __float2half_rn(wo[t]*r);
    }
    float r2 = r*r;
    float part[BATCH];
#pragma unroll
    for (int b = 0; b < BATCH; b++) part[b] = 0.f;
    for (int i = tid; i < CIN; i += 256) {
        float s9 = 0.f;
#pragma unroll
        for (int k = 0; k < 9; k++) { float v = wo[i*9+k]; s9 += v*v; }
        float w2 = s9*r2;
#pragma unroll
        for (int b = 0; b < BATCH; b++) {
            float sv = g_styles[b*CIN+i];
            part[b] += sv*sv*w2;
        }
    }
#pragma unroll
    for (int b = 0; b < BATCH; b++) {
        red[tid] = part[b]; __syncthreads();
        for (int s = 128; s > 0; s >>= 1) { if (tid < s) red[tid] += red[tid+s]; __syncthreads(); }
        if (tid == 0) g_d[b*COUT+o] = rsqrtf(red[0] + 1e-8f);
        __syncthreads();
    }
}

// ============ K_pad: vectorized (8 halves/thread, uint4 stores) ============
__global__ void k_pad(const float* __restrict__ x) {
    size_t t = (size_t)blockIdx.x*256 + threadIdx.x;
    if (t >= (size_t)BATCH*CIN*3*XSP/8) return;
    size_t base = t*8;
    int e0 = (int)(base % XSP);
    int dc = (int)((base / XSP) % 3);
    int bc = (int)(base / ((size_t)XSP*3));
    float sty = g_styles[bc];
    __half h[8];
    if (e0 < SPEC) {            // main region: row-aligned (72 % 8 == 0)
        int P = e0 / XPW, Q0 = e0 - P*XPW + dc;
        int ri = P - 2;
        bool rok = (ri >= 0 && ri < INS);
        const float* xr = x + ((size_t)bc*INS + ri)*INS;
#pragma unroll
        for (int j = 0; j < 8; j++) {
            int ci = Q0 + j - 2;
            float v = (rok && ci >= 0 && ci < INS) ? xr[ci]*sty : 0.f;
            h[j] = __float2half_rn(v);
        }
    } else {                    // special gathered atoms (per-element)
        int e2 = e0 - SPEC;
        int dr = e2 / 160, rem = e2 - dr*160;
        int s = rem >> 5, j0 = rem & 31;
        const int SA[5] = {32, 65, 98, 131, 136};
#pragma unroll
        for (int j = 0; j < 8; j++) {
            int PP, QQ; float v = 0.f;
            if (atom_pix(SA[s], j0 + j, PP, QQ)) {
                int ri = PP + dr - 2, ci = QQ + dc - 2;
                if (ri >= 0 && ri < INS && ci >= 0 && ci < INS)
                    v = x[((size_t)bc*INS + ri)*INS + ci]*sty;
            }
            h[j] = __float2half_rn(v);
        }
    }
    *(uint4*)(g_xs + base) = *(uint4*)h;
}

// ============ K_gemm: HMMA fp16, M=256 x N=128, 512 thr, 3-stage ============
// stage bytes: A[256][40h] = 20480 | B[32 rows][272B] = 8704  => 29184
#define STG_BYTES 29184
#define GEMM_SMEM (3*STG_BYTES)        // 87552
#define NCH 144

__global__ __launch_bounds__(512, 1)
void k_gemm(const float* __restrict__ cbias) {
    extern __shared__ __align__(16) char smraw[];
    uint32_t sb = smem_u32(smraw);
    int tid = threadIdx.x, w = tid >> 5, lane = tid & 31;
    int nt = blockIdx.x, oc0 = blockIdx.y * 256, bz = blockIdx.z;
    int m0 = (w & 3) * 64, n0 = (w >> 2) * 32;

    // ---- B cp.async geometry: thread -> (k_local, atom, 16B quarter) ----
    int k_local = tid >> 4;            // 0..31
    int a_local = (tid >> 2) & 3;      // 0..3
    int qq = tid & 3;                  // 16B quarter of 64B atom row
    int aG = nt*4 + a_local;
    int baseoff, drs; uint32_t csz;
    if (aG >= 137)                       { baseoff = 0; drs = 0; csz = 0; }
    else if (aG == 136)                  { baseoff = SPEC + 4*32; drs = 160; csz = 16; }
    else if (aG < 132 && (aG % 33) == 32){ baseoff = SPEC + (aG/33)*32; drs = 160; csz = 16; }
    else { int P, Q; atom_pix(aG, 0, P, Q); baseoff = P*XPW + Q; drs = XPW; csz = 16; }
    uint32_t bdst0 = (uint32_t)(20480 + k_local*272 + a_local*64 + qq*16);

    // ---- A geometry: thread t loads row t>>1, half t&1 (2x CP16) ----
    int arow = tid >> 1, ahalf = tid & 1;
    uint32_t adst0 = (uint32_t)((arow*40 + ahalf*16) * 2);

    // ---- ldmatrix base offsets (bytes from stage base) ----
    uint32_t a_base = (uint32_t)(((m0 + (lane & 15))*40 + ((lane >> 4)*8)) * 2);
    uint32_t b_base = (uint32_t)((10240 + ((lane & 7) + ((lane >> 3) & 1)*8)*136
                                  + n0 + ((lane >> 4)*8)) * 2);

    float acc[64];
#pragma unroll
    for (int t = 0; t < 64; t++) acc[t] = 0.f;

    auto issue = [&](int ch, int st) {
        // A: 256 rows x 64B
        const __half* asrc = g_wh + (size_t)(oc0 + arow)*KTOT + ch*32 + ahalf*16;
        uint32_t ad = sb + (uint32_t)(st*STG_BYTES) + adst0;
        CP16(ad,      asrc);
        CP16(ad + 16, asrc + 8);
        // B: 32 k-rows x 4 atoms x 64B
        int tap = ch >> 4, dr = tap/3, dc = tap - dr*3;
        int icb = (ch & 15) << 5;
        const __half* bsrc = g_xs
            + ((size_t)(bz*CIN + icb + k_local)*3 + dc)*XSP
            + baseoff + dr*drs + qq*8;
        uint32_t bd = sb + (uint32_t)(st*STG_BYTES) + bdst0;
        CP16Z(bd, bsrc, csz);
        CPC();
    };

    issue(0, 0);
    issue(1, 1);

    for (int ch = 0; ch < NCH; ch++) {
        int st = ch % 3;
        asm volatile("cp.async.wait_group 1;");
        __syncthreads();
        if (ch + 2 < NCH) issue(ch + 2, (ch + 2) % 3);

        uint32_t sbase = sb + (uint32_t)(st * STG_BYTES);
#pragma unroll
        for (int k16 = 0; k16 < 2; k16++) {
            uint32_t sA = sbase + a_base + k16*32;
            uint32_t sB = sbase + b_base + k16*(16*136*2);
            uint32_t ah[16], bh[8];
#pragma unroll
            for (int mt = 0; mt < 4; mt++) LDSM4(&ah[mt*4], sA + mt*1280);
#pragma unroll
            for (int n2 = 0; n2 < 2; n2++) LDSM4T(&bh[n2*4], sB + n2*32);
#pragma unroll
            for (int mt = 0; mt < 4; mt++)
#pragma unroll
                for (int n = 0; n < 4; n++)
                    MMA(&acc[(mt*4+n)*4], &ah[mt*4],
                        bh[(n>>1)*4 + (n&1)*2], bh[(n>>1)*4 + (n&1)*2 + 1]);
        }
    }

    // ---- epilogue: demod + bias, float2 stores ----
#pragma unroll
    for (int mt = 0; mt < 4; mt++) {
        int ocA = oc0 + m0 + mt*16 + (lane >> 2);
        float dmA = g_d[bz*COUT + ocA],     biA = cbias[ocA];
        float dmB = g_d[bz*COUT + ocA + 8], biB = cbias[ocA + 8];
        size_t rowA = ((size_t)(bz*COUT + ocA)) * PLANE;
        size_t rowB = rowA + (size_t)8 * PLANE;
#pragma unroll
        for (int n = 0; n < 4; n++) {
            int nl = n0 + n*8 + (lane & 3)*2;
            int P, Q;
            if (!atom_pix(nt*4 + (nl >> 5), nl & 31, P, Q)) continue;
            int po = P*Y1S + Q;
            float* c = &acc[(mt*4+n)*4];
            *(float2*)(g_y1 + rowA + po) = make_float2(c[0]*dmA + biA, c[1]*dmA + biA);
            *(float2*)(g_y1 + rowB + po) = make_float2(c[2]*dmB + biB, c[3]*dmB + biB);
        }
    }
}

// ============ K4: paired-polyphase fused FIR (fp16 act, stride 140) ======
// smem: vt 9108 f32 (36432B) | act 138x140 f16 (38640B) => 75072B, 3 CTAs/SM
#define K4_VT_BYTES  (9108*4)
#define K4_SMEM      (K4_VT_BYTES + 138*140*2)

__global__ __launch_bounds__(512, 3)
void k4_fir(float* __restrict__ out) {
    int plane = blockIdx.x, tid = threadIdx.x;
    extern __shared__ char sm4[];
    float*  vt  = (float*)sm4;
    __half* act = (__half*)(sm4 + K4_VT_BYTES);
    const float* src = g_y1 + (size_t)plane*PLANE;
    float fl[12];
#pragma unroll
    for (int k = 0; k < 12; k++) fl[k] = g_filter[k];

    // phase 1: vertical up-FIR, paired rows (2m, 2m+1). 69 pairs x 66 cols.
    for (int e = tid; e < 69*Y1S; e += 512) {
        int m = e / Y1S, i = e - m*Y1S;
        float s[6];
#pragma unroll
        for (int j = 0; j < 6; j++) {
            int row = m - 4 + j;
            s[j] = ((unsigned)row < 66u) ? src[row*Y1S + i] : 0.f;
        }
        float ev = s[0]*fl[10] + s[1]*fl[8] + s[2]*fl[6] + s[3]*fl[4] + s[4]*fl[2] + s[5]*fl[0];
        float od = s[0]*fl[11] + s[1]*fl[9] + s[2]*fl[7] + s[3]*fl[5] + s[4]*fl[3] + s[5]*fl[1];
        vt[(2*m)*Y1S + i]   = 4.f*ev;
        vt[(2*m+1)*Y1S + i] = 4.f*od;
    }
    __syncthreads();

    // phase 2: horizontal up-FIR + lrelu + clamp, paired cols. 138 x 69.
    for (int e = tid; e < UPS*69; e += 512) {
        int r = e / 69, m = e - r*69;
        const float* vr = vt + r*Y1S;
        float s[6];
#pragma unroll
        for (int j = 0; j < 6; j++) {
            int c = m - 4 + j;
            s[j] = ((unsigned)c < 66u) ? vr[c] : 0.f;
        }
        float ev = s[0]*fl[10] + s[1]*fl[8] + s[2]*fl[6] + s[3]*fl[4] + s[4]*fl[2] + s[5]*fl[0];
        float od = s[0]*fl[11] + s[1]*fl[9] + s[2]*fl[7] + s[3]*fl[5] + s[4]*fl[3] + s[5]*fl[1];
        ev = (ev >= 0.f ? ev : 0.2f*ev)*1.4142135623730951f;
        od = (od >= 0.f ? od : 0.2f*od)*1.4142135623730951f;
        ev = fminf(fmaxf(ev, -256.f), 256.f);
        od = fminf(fmaxf(od, -256.f), 256.f);
        *(__half2*)(act + r*140 + 2*m) = __floats2half2_rn(ev, od);
    }
    __syncthreads();

    // phase 3: vertical down-FIR (stride-2 rows), half2 col pairs. 64 x 69.
    for (int e = tid; e < OUTS*69; e += 512) {
        int rr = e / 69, jj = e - rr*69;
        const __half2* ap = (const __half2*)(act + (2*rr)*140 + 2*jj);
        float ax = 0.f, ay = 0.f;
#pragma unroll
        for (int t = 0; t < 12; t++) {
            float2 v = __half22float2(ap[t*70]);
            ax += fl[11-t]*v.x;
            ay += fl[11-t]*v.y;
        }
        *(float2*)(vt + rr*UPS + 2*jj) = make_float2(ax, ay);
    }
    __syncthreads();

    // phase 4: horizontal down-FIR (stride 2), paired outputs. 64 x 32.
    float* dst = out + (size_t)plane*(OUTS*OUTS);
    for (int e = tid; e < OUTS*32; e += 512) {
        int rr = e >> 5, p = e & 31;
        const float* dp = vt + rr*UPS + 4*p;
        float d[14];
#pragma unroll
        for (int q = 0; q < 14; q++) d[q] = dp[q];
        float o0 = 0.f, o1 = 0.f;
#pragma unroll
        for (int t = 0; t < 12; t++) {
            o0 += fl[11-t]*d[t];
            o1 += fl[11-t]*d[t+2];
        }
        *(float2*)(dst + rr*OUTS + 2*p) = make_float2(o0, o1);
    }
}

// ============ launch ============
extern "C" void kernel_launch(void* const* d_in, const int* in_sizes, int n_in,
                              void* d_out, int out_size) {
    const float* x  = (const float*)d_in[0];
    const float* w  = (const float*)d_in[1];
    const float* A  = (const float*)d_in[2];
    const float* ab = (const float*)d_in[3];
    const float* cw = (const float*)d_in[4];
    const float* cb = (const float*)d_in[5];
    float* out = (float*)d_out;

    cudaFuncSetAttribute(k_gemm, cudaFuncAttributeMaxDynamicSharedMemorySize, GEMM_SMEM);
    cudaFuncSetAttribute(k4_fir, cudaFuncAttributeMaxDynamicSharedMemorySize, K4_SMEM);

    size_t nvec = (size_t)BATCH*CIN*3*XSP/8;
    k0_styles<<<1, 512>>>(w, A, ab);
    k1_wnorm<<<COUT, 256>>>(cw);
    k_pad<<<(unsigned)((nvec + 255)/256), 256>>>(x);
    k_gemm<<<dim3(35, 2, BATCH), 512, GEMM_SMEM>>>(cb);   // launch idx 3
    k4_fir<<<BATCH*COUT, 512, K4_SMEM>>>(out);
}